// round 9
// baseline (speedup 1.0000x reference)
#include <cuda_runtime.h>
#include <math.h>
#include <stdint.h>

#define D_MODEL 512
#define BATCH   4
#define SEQ     2048
#define TOK     (BATCH * SEQ)   // 8192

// ---- scratch (allocation-free: static device globals) ----
__device__ float g_qkv[3 * TOK * D_MODEL];           // 48 MiB (Q | K | V)
__device__ float g_att[TOK * D_MODEL];               // 16 MiB
__device__ float g_s[(size_t)BATCH * SEQ * SEQ];     // 64 MiB

// ---- PTX helpers ----
__device__ __forceinline__ void cp_async16(uint32_t dst_smem, const void* src) {
    asm volatile("cp.async.cg.shared.global [%0], [%1], 16;\n"
                 :: "r"(dst_smem), "l"(src) : "memory");
}
__device__ __forceinline__ void cp_commit() {
    asm volatile("cp.async.commit_group;\n" ::: "memory");
}
__device__ __forceinline__ void cp_wait0() {
    asm volatile("cp.async.wait_group 0;\n" ::: "memory");
}
__device__ __forceinline__ uint32_t to_tf32(float x) {
    uint32_t r;
    asm("cvt.rna.tf32.f32 %0, %1;" : "=r"(r) : "f"(x));
    return r;
}
// 3xTF32 split: x ~= hi + lo, hi/lo both tf32 (fp32-bit-layout, low mantissa 0)
__device__ __forceinline__ void tf32_split(float x, uint32_t& hi, uint32_t& lo) {
    hi = to_tf32(x);
    lo = to_tf32(x - __uint_as_float(hi));
}
// m16n8k8 tf32 MMA: A 4 regs, B 2 regs, C 4 fp32
__device__ __forceinline__ void mma_tf32_k8(float acc[4], const uint32_t a[4],
                                            const uint32_t b[2]) {
    asm volatile(
        "mma.sync.aligned.m16n8k8.row.col.f32.tf32.tf32.f32 "
        "{%0,%1,%2,%3}, {%4,%5,%6,%7}, {%8,%9}, {%0,%1,%2,%3};\n"
        : "+f"(acc[0]), "+f"(acc[1]), "+f"(acc[2]), "+f"(acc[3])
        : "r"(a[0]), "r"(a[1]), "r"(a[2]), "r"(a[3]), "r"(b[0]), "r"(b[1]));
}

// ============================================================================
// 3xTF32 tensor-core GEMM body (mma.sync m16n8k8), cp.async double-buffered.
//   TRANSB = true :  C[m][n] = scale * sum_k A[m][k] * B[n][k]  (+ bias[n])
//   TRANSB = false:  C[m][n] = scale * sum_k A[m][k] * B[k][n]  (+ bias[n])
// BM=BN=128, BK=16, 256 threads = 8 warps (2x4). Warp tile 64x32.
// Each product computed as lo*hi + hi*lo + hi*hi (fp32-class accuracy).
// MMA issue order: term-outermost -> 16 independent accumulator chains
// back-to-back per term (dependency distance 16, not 1).
// Pointers must already be offset for the batch; m0/n0 from blockIdx.y/x.
// ============================================================================
template <bool TRANSB, bool BIAS>
__device__ __forceinline__
void gemm_tc_body(const float* __restrict__ A, const float* __restrict__ Bm,
                  const float* __restrict__ bias, float* __restrict__ C,
                  int Nn, int K, float scale)
{
    constexpr int BM = 128, BN = 128, BK = 16;
    constexpr int AS_STRIDE = 20;   // words per A row  (pad 4: conflict-free, 16B-aligned)
    constexpr int BT_STRIDE = 20;   // words per Bs row (TRANSB: [n][k])
    constexpr int BN_STRIDE = 132;  // words per Bs row (NN:    [k][n], pad 4)
    constexpr int BS_WORDS  = TRANSB ? (BN * BT_STRIDE) : (BK * BN_STRIDE);

    __shared__ float As[2][BM * AS_STRIDE];
    __shared__ float Bs[2][BS_WORDS];

    const int tid  = threadIdx.x;
    const int wid  = tid >> 5;
    const int lane = tid & 31;
    const int g    = lane >> 2;     // group id 0..7
    const int c    = lane & 3;      // thread-in-group 0..3
    const int wm   = wid >> 2;      // warp m row 0..1
    const int wn   = wid & 3;       // warp n col 0..3

    const int m0 = blockIdx.y * BM;
    const int n0 = blockIdx.x * BN;

    float acc[4][4][4];             // [mt][nt][frag]
#pragma unroll
    for (int mt = 0; mt < 4; mt++)
#pragma unroll
        for (int nt = 0; nt < 4; nt++)
#pragma unroll
            for (int r = 0; r < 4; r++) acc[mt][nt][r] = 0.0f;

    const uint32_t as_base[2] = {
        (uint32_t)__cvta_generic_to_shared(&As[0][0]),
        (uint32_t)__cvta_generic_to_shared(&As[1][0]) };
    const uint32_t bs_base[2] = {
        (uint32_t)__cvta_generic_to_shared(&Bs[0][0]),
        (uint32_t)__cvta_generic_to_shared(&Bs[1][0]) };

    // ---- tile copy: 512 16B-chunks each for A and B, 2 per thread each ----
    auto copy_tile = [&](int k0, int buf) {
#pragma unroll
        for (int i = 0; i < 2; i++) {             // A: [BM][BK] from [M][K]
            const int chunk = tid + i * 256;      // 0..511
            const int row = chunk >> 2;           // 4 chunks (16 floats) per row
            const int c4  = (chunk & 3) << 2;
            cp_async16(as_base[buf] + (uint32_t)(row * AS_STRIDE + c4) * 4,
                       &A[(size_t)(m0 + row) * K + k0 + c4]);
        }
        if (TRANSB) {
#pragma unroll
            for (int i = 0; i < 2; i++) {         // B: [BN][BK] from [N][K]
                const int chunk = tid + i * 256;
                const int row = chunk >> 2;
                const int c4  = (chunk & 3) << 2;
                cp_async16(bs_base[buf] + (uint32_t)(row * BT_STRIDE + c4) * 4,
                           &Bm[(size_t)(n0 + row) * K + k0 + c4]);
            }
        } else {
#pragma unroll
            for (int i = 0; i < 2; i++) {         // B: [BK][BN] from [K][N]
                const int chunk = tid + i * 256;
                const int row = chunk >> 5;       // 32 chunks (128 floats) per row
                const int n4  = (chunk & 31) << 2;
                cp_async16(bs_base[buf] + (uint32_t)(row * BN_STRIDE + n4) * 4,
                           &Bm[(size_t)(k0 + row) * Nn + n0 + n4]);
            }
        }
    };

    // ---- prologue ----
    copy_tile(0, 0);
    cp_commit();

    const int ksteps = K / BK;
    int buf = 0;
    for (int step = 0; step < ksteps; step++) {
        cp_wait0();
        __syncthreads();               // tile[step] visible; prev compute finished
        if (step + 1 < ksteps) {
            copy_tile((step + 1) * BK, buf ^ 1);
            cp_commit();
        }

        // ---- compute tile[step]: two k8 chunks ----
        const float* Ab = As[buf];
        const float* Bb = Bs[buf];
#pragma unroll
        for (int kc = 0; kc < 2; kc++) {
            const int col0 = kc * 8 + c;          // k for a0/a1, b0
            const int col1 = col0 + 4;            // k for a2/a3, b1

            // A fragments (4 regs each), split hi/lo
            uint32_t afh[4][4], afl[4][4];
#pragma unroll
            for (int mt = 0; mt < 4; mt++) {
                const int r0 = wm * 64 + mt * 16 + g;
                tf32_split(Ab[(r0    ) * AS_STRIDE + col0], afh[mt][0], afl[mt][0]);
                tf32_split(Ab[(r0 + 8) * AS_STRIDE + col0], afh[mt][1], afl[mt][1]);
                tf32_split(Ab[(r0    ) * AS_STRIDE + col1], afh[mt][2], afl[mt][2]);
                tf32_split(Ab[(r0 + 8) * AS_STRIDE + col1], afh[mt][3], afl[mt][3]);
            }
            // B fragments (2 regs each), split hi/lo
            uint32_t bfh[4][2], bfl[4][2];
#pragma unroll
            for (int nt = 0; nt < 4; nt++) {
                const int nn = wn * 32 + nt * 8 + g;
                const float b0 = TRANSB ? Bb[nn * BT_STRIDE + col0]
                                        : Bb[col0 * BN_STRIDE + nn];
                const float b1 = TRANSB ? Bb[nn * BT_STRIDE + col1]
                                        : Bb[col1 * BN_STRIDE + nn];
                tf32_split(b0, bfh[nt][0], bfl[nt][0]);
                tf32_split(b1, bfh[nt][1], bfl[nt][1]);
            }

            // term-outermost: 16 independent MMAs per term; per-accumulator
            // order is still ll -> hl -> hh (bit-identical to round 8)
#pragma unroll
            for (int mt = 0; mt < 4; mt++)
#pragma unroll
                for (int nt = 0; nt < 4; nt++)
                    mma_tf32_k8(acc[mt][nt], afl[mt], bfh[nt]);
#pragma unroll
            for (int mt = 0; mt < 4; mt++)
#pragma unroll
                for (int nt = 0; nt < 4; nt++)
                    mma_tf32_k8(acc[mt][nt], afh[mt], bfl[nt]);
#pragma unroll
            for (int mt = 0; mt < 4; mt++)
#pragma unroll
                for (int nt = 0; nt < 4; nt++)
                    mma_tf32_k8(acc[mt][nt], afh[mt], bfh[nt]);
        }
        buf ^= 1;
    }

    // ---- epilogue: scale + bias, float2 stores ----
#pragma unroll
    for (int nt = 0; nt < 4; nt++) {
        const int colb = n0 + wn * 32 + nt * 8 + c * 2;
        float2 bv = make_float2(0.0f, 0.0f);
        if (BIAS) { bv.x = bias[colb]; bv.y = bias[colb + 1]; }
#pragma unroll
        for (int mt = 0; mt < 4; mt++) {
            const int r0 = m0 + wm * 64 + mt * 16 + g;
            float2 lo = make_float2(fmaf(acc[mt][nt][0], scale, bv.x),
                                    fmaf(acc[mt][nt][1], scale, bv.y));
            float2 hi = make_float2(fmaf(acc[mt][nt][2], scale, bv.x),
                                    fmaf(acc[mt][nt][3], scale, bv.y));
            *(float2*)&C[(size_t)(r0    ) * Nn + colb] = lo;
            *(float2*)&C[(size_t)(r0 + 8) * Nn + colb] = hi;
        }
    }
}

// Generic batched wrapper (blockIdx.z strides over batch)
template <bool TRANSB, bool BIAS>
__global__ __launch_bounds__(256, 2)
void gemm_tc(const float* __restrict__ A, const float* __restrict__ Bm,
             const float* __restrict__ bias, float* __restrict__ C,
             int Nn, int K, float scale,
             size_t sA, size_t sB, size_t sC)
{
    gemm_tc_body<TRANSB, BIAS>(A + (size_t)blockIdx.z * sA,
                               Bm + (size_t)blockIdx.z * sB,
                               bias,
                               C + (size_t)blockIdx.z * sC,
                               Nn, K, scale);
}

// Fused Q/K/V projection: blockIdx.z in {0,1,2} selects weights/bias/output.
// One launch = 768 CTAs (fills the chip) instead of 3 under-full 256-CTA waves.
__global__ __launch_bounds__(256, 2)
void gemm_proj3(const float* __restrict__ x,
                const float* __restrict__ Wq, const float* __restrict__ bq,
                const float* __restrict__ Wk, const float* __restrict__ bk,
                const float* __restrict__ Wv, const float* __restrict__ bv,
                float* __restrict__ qkv)
{
    const int z = blockIdx.z;
    const float* W = (z == 0) ? Wq : (z == 1) ? Wk : Wv;
    const float* b = (z == 0) ? bq : (z == 1) ? bk : bv;
    float* C = qkv + (size_t)z * TOK * D_MODEL;
    gemm_tc_body<true, true>(x, W, b, C, D_MODEL, D_MODEL, 1.0f);
}

// ============================================================================
// Row softmax over rows of length SEQ (2048). One block (256 threads) per row.
// __expf (MUFU.EX2): inputs <= 0 after max subtraction; normalization cancels
// residual common-mode error.
// ============================================================================
__global__ __launch_bounds__(256)
void softmax_kernel(float* __restrict__ S)
{
    const size_t row = blockIdx.x;
    float4* p4 = (float4*)(S + row * (size_t)SEQ);
    const int tid = threadIdx.x;
    const int lane = tid & 31;
    const int wid = tid >> 5;

    float4 v0 = p4[tid];
    float4 v1 = p4[tid + 256];

    // ---- max ----
    float m = fmaxf(fmaxf(fmaxf(v0.x, v0.y), fmaxf(v0.z, v0.w)),
                    fmaxf(fmaxf(v1.x, v1.y), fmaxf(v1.z, v1.w)));
#pragma unroll
    for (int off = 16; off > 0; off >>= 1)
        m = fmaxf(m, __shfl_xor_sync(0xFFFFFFFFu, m, off));

    __shared__ float red[8];
    if (lane == 0) red[wid] = m;
    __syncthreads();
    m = red[0];
#pragma unroll
    for (int w = 1; w < 8; w++) m = fmaxf(m, red[w]);
    __syncthreads();

    // ---- exp + sum ----
    v0.x = __expf(v0.x - m); v0.y = __expf(v0.y - m);
    v0.z = __expf(v0.z - m); v0.w = __expf(v0.w - m);
    v1.x = __expf(v1.x - m); v1.y = __expf(v1.y - m);
    v1.z = __expf(v1.z - m); v1.w = __expf(v1.w - m);

    float s = (v0.x + v0.y + v0.z + v0.w) + (v1.x + v1.y + v1.z + v1.w);
#pragma unroll
    for (int off = 16; off > 0; off >>= 1)
        s += __shfl_xor_sync(0xFFFFFFFFu, s, off);

    __shared__ float reds[8];
    if (lane == 0) reds[wid] = s;
    __syncthreads();
    s = reds[0];
#pragma unroll
    for (int w = 1; w < 8; w++) s += reds[w];

    const float inv = 1.0f / s;
    v0.x *= inv; v0.y *= inv; v0.z *= inv; v0.w *= inv;
    v1.x *= inv; v1.y *= inv; v1.z *= inv; v1.w *= inv;

    p4[tid] = v0;
    p4[tid + 256] = v1;
}

// ============================================================================
// Launch
// ============================================================================
extern "C" void kernel_launch(void* const* d_in, const int* in_sizes, int n_in,
                              void* d_out, int out_size)
{
    (void)in_sizes; (void)n_in; (void)out_size;
    const float* x  = (const float*)d_in[0];
    const float* Wq = (const float*)d_in[1];
    const float* bq = (const float*)d_in[2];
    const float* Wk = (const float*)d_in[3];
    const float* bk = (const float*)d_in[4];
    const float* Wv = (const float*)d_in[5];
    const float* bv = (const float*)d_in[6];
    const float* Wo = (const float*)d_in[7];
    const float* bo = (const float*)d_in[8];
    float* out = (float*)d_out;

    float *qkvp, *sp, *ap;
    cudaGetSymbolAddress((void**)&qkvp, g_qkv);
    cudaGetSymbolAddress((void**)&sp, g_s);
    cudaGetSymbolAddress((void**)&ap, g_att);
    float* qp = qkvp;
    float* kp = qkvp + (size_t)TOK * D_MODEL;
    float* vp = qkvp + 2 * (size_t)TOK * D_MODEL;

    const dim3 blk(256);
    const float inv_sqrt_d = 0.04419417382415922f;   // 1/sqrt(512)

    // Fused Q/K/V projections: [8192,512] = x @ W^T + b, z selects {q,k,v}
    const dim3 gp3(D_MODEL / 128, TOK / 128, 3);     // (4, 64, 3) = 768 CTAs
    gemm_proj3<<<gp3, blk>>>(x, Wq, bq, Wk, bk, Wv, bv, qkvp);

    // scores: per batch [2048,2048] = Q @ K^T * scale
    const dim3 gsc(SEQ / 128, SEQ / 128, BATCH);     // (16, 16, 4)
    gemm_tc<true, false><<<gsc, blk>>>(qp, kp, nullptr, sp,
                                       SEQ, D_MODEL, inv_sqrt_d,
                                       (size_t)SEQ * D_MODEL,
                                       (size_t)SEQ * D_MODEL,
                                       (size_t)SEQ * SEQ);

    // softmax over 8192 rows of length 2048
    softmax_kernel<<<TOK, blk>>>(sp);

    // att: per batch [2048,512] = P[2048,2048] @ V[2048,512]
    const dim3 gav(D_MODEL / 128, SEQ / 128, BATCH); // (4, 16, 4)
    gemm_tc<false, false><<<gav, blk>>>(sp, vp, nullptr, ap,
                                        D_MODEL, SEQ, 1.0f,
                                        (size_t)SEQ * SEQ,
                                        (size_t)SEQ * D_MODEL,
                                        (size_t)SEQ * D_MODEL);

    // output projection: [8192,512] = att @ Wo^T + bo
    const dim3 gproj(D_MODEL / 128, TOK / 128, 1);   // (4, 64)
    gemm_tc<true, true><<<gproj, blk>>>(ap, Wo, bo, out,
                                        D_MODEL, D_MODEL, 1.0f, 0, 0, 0);
}